// round 8
// baseline (speedup 1.0000x reference)
#include <cuda_runtime.h>
#include <cuda_bf16.h>
#include <math.h>
#include <stdint.h>

#define CNW 64
#define KN 1024
#define NPTS 65536
#define PLANE 1024
#define ZSZ 4194304
#define EPSV 1e-10f
#define TRIGM 1.5e-3f         // packed-bf16 trigger margin
#define EMITM 1.2e-3f         // f32 emission margin
#define LISTCAP 24
#define PITCHW 36             // u32 words per row in smem A/B tiles (64 bf16 + pad)

typedef unsigned long long ull;

__device__ float    g_cnorm[KN];
__device__ int      g_hist[KN];
__device__ unsigned g_cbbf[KN * 32];   // packed bf16 pairs, 32 words/row

// ---------------- smem layout (bytes) ----------------
// SM_A region is ALIASED by CAND/CNT/BESTS/FBROWS/FBCNT/FBBEST — those may only
// be touched AFTER the A fragments are loaded into registers.
#define SM_B0      0                       // 18432
#define SM_B1      18432                   // 18432
#define SM_EN      36864                   // float[1024] = 4096 (-norm/2)
#define SM_A       40960                   // 18432
#define SM_CAND    40960                   // u16[128*24] = 6144
#define SM_CNT     47104                   // int[128]
#define SM_BESTS   47616                   // int[128]
#define SM_FBROWS  48128                   // int[128]
#define SM_FBCNT   48640
#define SM_FBBEST  48648
#define SM_TOTAL   59392

// ---------------------------------------------------------------------------
__global__ void k_prep(const float* __restrict__ cb) {
    int row  = blockIdx.x * 8 + (threadIdx.x >> 5);
    int lane = threadIdx.x & 31;
    if (row >= KN) return;
    const float* r = cb + row * CNW;
    float e0 = r[2 * lane], e1 = r[2 * lane + 1];
    float s = __fmaf_rn(e0, e0, __fmul_rn(e1, e1));
    #pragma unroll
    for (int o = 16; o; o >>= 1) s += __shfl_xor_sync(0xffffffffu, s, o);
    g_cbbf[row * 32 + lane] =
        (unsigned)__bfloat16_as_ushort(__float2bfloat16(e0))
      | ((unsigned)__bfloat16_as_ushort(__float2bfloat16(e1)) << 16);
    if (lane == 0) { g_cnorm[row] = s; g_hist[row] = 0; }
}

// ---------------------------------------------------------------------------
__device__ __forceinline__ void mma16816(float& d0, float& d1, float& d2, float& d3,
                                         unsigned a0, unsigned a1, unsigned a2, unsigned a3,
                                         unsigned b0, unsigned b1) {
    asm volatile(
        "mma.sync.aligned.m16n8k16.row.col.f32.bf16.bf16.f32 "
        "{%0,%1,%2,%3}, {%4,%5,%6,%7}, {%8,%9}, {%0,%1,%2,%3};"
        : "+f"(d0), "+f"(d1), "+f"(d2), "+f"(d3)
        : "r"(a0), "r"(a1), "r"(a2), "r"(a3), "r"(b0), "r"(b1));
}

__device__ __forceinline__ unsigned pack_bf2(float lo, float hi) {
    unsigned p;
    asm("cvt.rn.bf16x2.f32 %0, %1, %2;" : "=r"(p) : "f"(hi), "f"(lo));
    return p;
}
__device__ __forceinline__ unsigned max_bf2(unsigned a, unsigned b) {
    unsigned m;
    asm("max.bf16x2 %0, %1, %2;" : "=r"(m) : "r"(a), "r"(b));
    return m;
}
__device__ __forceinline__ float bf2_lo(unsigned p) { return __uint_as_float(p << 16); }
__device__ __forceinline__ float bf2_hi(unsigned p) { return __uint_as_float(p & 0xffff0000u); }

// exact reference-rounded distance: d = RN(RN(xn+en) + RN(-2*dot)), seq fma chain
__device__ __forceinline__ float exactDist(const float* __restrict__ zp,
                                           const float* __restrict__ crow,
                                           float xn, float en) {
    float dot = 0.0f;
    #pragma unroll
    for (int c = 0; c < CNW; c++) dot = __fmaf_rn(zp[c * PLANE], crow[c], dot);
    return __fadd_rn(__fadd_rn(xn, en), __fmul_rn(-2.0f, dot));
}

// ---------------------------------------------------------------------------
// main: bf16 HMMA (argmax x.e - en/2, bias in accumulator init), chunk-deferred
// register-resident packed scan. CTA = 128 points, 256 threads, occ 3.
// ---------------------------------------------------------------------------
__global__ __launch_bounds__(256, 3)
void k_main(const float* __restrict__ z, const float* __restrict__ cb,
            float* __restrict__ out) {
    extern __shared__ char smem[];
    unsigned*       b0S = (unsigned*)(smem + SM_B0);
    unsigned*       b1S = (unsigned*)(smem + SM_B1);
    float*          enS = (float*)(smem + SM_EN);
    unsigned*       aS  = (unsigned*)(smem + SM_A);
    unsigned short* candK = (unsigned short*)(smem + SM_CAND);
    int* cnt    = (int*)(smem + SM_CNT);
    int* bests  = (int*)(smem + SM_BESTS);
    int* fbRows = (int*)(smem + SM_FBROWS);
    int* fbCnt  = (int*)(smem + SM_FBCNT);
    ull* fbBest = (ull*)(smem + SM_FBBEST);

    const int tid  = threadIdx.x;
    const int lane = tid & 31;
    const int warp = tid >> 5;
    const int n0   = blockIdx.x * 128;
    const float* zb = z + (size_t)(n0 >> 10) * (CNW * PLANE) + (n0 & 1023);

    // ---- stage A (z -> bf16 pairs, pitch 36) + en (-norm/2) + B chunk 0 ----
    for (int i = tid; i < 128 * 32; i += 256) {
        int j = i >> 7, p = i & 127;
        float lo = zb[(2 * j) * PLANE + p];
        float hi = zb[(2 * j + 1) * PLANE + p];
        aS[p * PITCHW + j] =
            (unsigned)__bfloat16_as_ushort(__float2bfloat16(lo))
          | ((unsigned)__bfloat16_as_ushort(__float2bfloat16(hi)) << 16);
    }
    for (int i = tid; i < KN; i += 256) enS[i] = -0.5f * g_cnorm[i];
    {
        const uint4* src = (const uint4*)g_cbbf;
        uint4* dst = (uint4*)b0S;
        for (int i = tid; i < 1024; i += 256) {
            int kr = i >> 3, q = i & 7;
            dst[kr * 9 + q] = src[i];
        }
    }
    __syncthreads();

    // ---- A fragments in registers ----
    const int r = lane >> 2, t = lane & 3;
    const int m0 = warp * 16;
    unsigned a[4][4];
    #pragma unroll
    for (int c5 = 0; c5 < 4; c5++) {
        int w0 = (m0 + r) * PITCHW + c5 * 8 + t;
        int w1 = w0 + 8 * PITCHW;
        a[c5][0] = aS[w0]; a[c5][1] = aS[w1];
        a[c5][2] = aS[w0 + 4]; a[c5][3] = aS[w1 + 4];
    }
    __syncthreads();     // A staging dead; aliased bookkeeping may now be init'd
    if (tid < 128) cnt[tid] = 0;
    if (tid == 128) *fbCnt = 0;
    __syncthreads();

    const int row0 = m0 + r, row1 = row0 + 8;
    float rm0 = -1e30f, rm1 = -1e30f;

    for (int ch = 0; ch < 8; ch++) {
        if (ch + 1 < 8) {   // stage next B chunk into the other buffer
            const uint4* src = (const uint4*)(g_cbbf + (size_t)(ch + 1) * 128 * 32);
            uint4* dst = (uint4*)(((ch + 1) & 1) ? b1S : b0S);
            for (int i = tid; i < 1024; i += 256) {
                int kr = i >> 3, q = i & 7;
                dst[kr * 9 + q] = src[i];
            }
        }
        const unsigned* bS = (ch & 1) ? b1S : b0S;
        const int kb = ch * 128;

        #pragma unroll 1
        for (int half = 0; half < 2; half++) {
            // ---- pass A: MMAs (bias-initialized acc), packed running max ----
            unsigned sc0[8], sc1[8];
            unsigned pm0 = 0xFF80FF80u, pm1 = 0xFF80FF80u;   // (-inf,-inf)
            #pragma unroll
            for (int n8 = 0; n8 < 8; n8++) {
                const int nt = half * 8 + n8;
                float2 enh = *(const float2*)&enS[kb + nt * 8 + 2 * t];
                float d0 = enh.x, d1 = enh.y, d2 = enh.x, d3 = enh.y;
                const int base = (nt * 8 + r) * PITCHW + t;
                #pragma unroll
                for (int c5 = 0; c5 < 4; c5++) {
                    unsigned bb0 = bS[base + c5 * 8];
                    unsigned bb1 = bS[base + c5 * 8 + 4];
                    mma16816(d0, d1, d2, d3,
                             a[c5][0], a[c5][1], a[c5][2], a[c5][3], bb0, bb1);
                }
                unsigned p0 = pack_bf2(d0, d1);   // row0: k0(lo), k0+1(hi)
                unsigned p1 = pack_bf2(d2, d3);   // row1
                pm0 = max_bf2(pm0, p0);
                pm1 = max_bf2(pm1, p1);
                sc0[n8] = p0; sc1[n8] = p1;
            }

            // ---- sub-chunk max per row (quad reduce), monotone running max ----
            float m0f = fmaxf(bf2_lo(pm0), bf2_hi(pm0));
            float m1f = fmaxf(bf2_lo(pm1), bf2_hi(pm1));
            m0f = fmaxf(m0f, __shfl_xor_sync(0xffffffffu, m0f, 1));
            m0f = fmaxf(m0f, __shfl_xor_sync(0xffffffffu, m0f, 2));
            m1f = fmaxf(m1f, __shfl_xor_sync(0xffffffffu, m1f, 1));
            m1f = fmaxf(m1f, __shfl_xor_sync(0xffffffffu, m1f, 2));
            rm0 = fmaxf(rm0, m0f);
            rm1 = fmaxf(rm1, m1f);

            // ---- pass B: packed threshold scan of register scores ----
            const float th0e = rm0 - EMITM, th1e = rm1 - EMITM;
            const unsigned thr0 = pack_bf2(rm0 - TRIGM, rm0 - TRIGM);
            const unsigned thr1 = pack_bf2(rm1 - TRIGM, rm1 - TRIGM);
            #pragma unroll
            for (int n8 = 0; n8 < 8; n8++) {
                const int k0 = kb + (half * 8 + n8) * 8 + 2 * t;
                unsigned v0 = sc0[n8];
                if (max_bf2(v0, thr0) != thr0) {
                    if (bf2_lo(v0) >= th0e) {
                        int pos = atomicAdd(&cnt[row0], 1);
                        if (pos < LISTCAP) candK[row0 * LISTCAP + pos] = (unsigned short)k0;
                    }
                    if (bf2_hi(v0) >= th0e) {
                        int pos = atomicAdd(&cnt[row0], 1);
                        if (pos < LISTCAP) candK[row0 * LISTCAP + pos] = (unsigned short)(k0 + 1);
                    }
                }
                unsigned v1 = sc1[n8];
                if (max_bf2(v1, thr1) != thr1) {
                    if (bf2_lo(v1) >= th1e) {
                        int pos = atomicAdd(&cnt[row1], 1);
                        if (pos < LISTCAP) candK[row1 * LISTCAP + pos] = (unsigned short)k0;
                    }
                    if (bf2_hi(v1) >= th1e) {
                        int pos = atomicAdd(&cnt[row1], 1);
                        if (pos < LISTCAP) candK[row1 * LISTCAP + pos] = (unsigned short)(k0 + 1);
                    }
                }
            }
        }
        __syncthreads();   // staged buffer visible; readers done before overwrite
    }

    // ---- phase 2: exact recheck (reference-rounded) ----
    if (tid < 128) {
        int c = cnt[tid];
        if (c > LISTCAP || c == 0) {
            fbRows[atomicAdd(fbCnt, 1)] = tid;
        } else {
            const float* zp = zb + tid;
            float xn = 0.0f;
            #pragma unroll
            for (int cc = 0; cc < CNW; cc++) {
                float x = zp[cc * PLANE];
                xn = __fadd_rn(xn, __fmul_rn(x, x));
            }
            float bd = 1e30f; int bk = 0x7fffffff;
            for (int j = 0; j < c; j++) {
                int k = candK[tid * LISTCAP + j];
                float d = exactDist(zp, cb + (size_t)k * CNW, xn, g_cnorm[k]);
                if (d < bd || (d == bd && k < bk)) { bd = d; bk = k; }
            }
            bests[tid] = bk;
            out[(size_t)2 * ZSZ + n0 + tid] = (float)bk;
            atomicAdd(&g_hist[bk], 1);
        }
    }
    __syncthreads();

    // ---- fallback: CTA-cooperative exact scan (provably-safe net, ~never) ----
    int nfb = *fbCnt;
    if (nfb > 128) nfb = 128;
    for (int f = 0; f < nfb; f++) {
        const int row = fbRows[f];
        if (tid == 0) *fbBest = ~0ull;
        __syncthreads();
        const float* zp = zb + row;
        float xn = 0.0f;
        #pragma unroll
        for (int cc = 0; cc < CNW; cc++) {
            float x = zp[cc * PLANE];
            xn = __fadd_rn(xn, __fmul_rn(x, x));
        }
        for (int k = tid; k < KN; k += 256) {
            float d = exactDist(zp, cb + (size_t)k * CNW, xn, g_cnorm[k]);
            ull pk = ((ull)__float_as_uint(d) << 32) | (unsigned)k;   // d > 0
            atomicMin(fbBest, pk);
        }
        __syncthreads();
        if (tid == 0) {
            int bk = (int)(*fbBest & 0xffffffffull);
            bests[row] = bk;
            out[(size_t)2 * ZSZ + n0 + row] = (float)bk;
            atomicAdd(&g_hist[bk], 1);
        }
        __syncthreads();
    }
    __syncthreads();

    // ---- phase 3: gather rows to smem (reuse B region), coalesced writes ----
    float* qs = (float*)(smem + SM_B0);   // 128 x pitch-65 floats = 33280B
    for (int i = tid; i < 128 * 64; i += 256) {
        int p = i >> 6, c = i & 63;
        qs[p * 65 + c] = cb[(size_t)bests[p] * CNW + c];
    }
    __syncthreads();
    const size_t obase = (size_t)(n0 >> 10) * (CNW * PLANE) + (n0 & 1023);
    for (int i = tid; i < 128 * 64; i += 256) {
        int c = i >> 7, p = i & 127;
        float q = qs[p * 65 + c];
        float x = zb[c * PLANE + p];
        size_t o = obase + (size_t)c * PLANE + p;
        out[o]       = q;
        out[o + ZSZ] = __fadd_rn(x, __fsub_rn(q, x));   // z + (q - z)
    }
}

// ---------------------------------------------------------------------------
__global__ void k_perp(float* __restrict__ out) {
    __shared__ float red[32];
    int t = threadIdx.x;
    float p = (float)g_hist[t] * (1.0f / (float)NPTS);
    float term = __fmul_rn(p, logf(fmaxf(p, EPSV)));
    #pragma unroll
    for (int o = 16; o; o >>= 1) term += __shfl_xor_sync(0xffffffffu, term, o);
    if ((t & 31) == 0) red[t >> 5] = term;
    __syncthreads();
    if (t < 32) {
        float s = red[t];
        #pragma unroll
        for (int o = 16; o; o >>= 1) s += __shfl_xor_sync(0xffffffffu, s, o);
        if (t == 0) out[(size_t)2 * ZSZ + NPTS] = expf(-s);
    }
}

// ---------------------------------------------------------------------------
extern "C" void kernel_launch(void* const* d_in, const int* in_sizes, int n_in,
                              void* d_out, int out_size) {
    const float* z  = (const float*)d_in[0];
    const float* cb = (const float*)d_in[1];
    if (n_in >= 2 && in_sizes[0] == KN * CNW && in_sizes[1] == ZSZ) {
        const float* tmp = z; z = cb; cb = tmp;
    }
    float* out = (float*)d_out;

    cudaFuncSetAttribute(k_main, cudaFuncAttributeMaxDynamicSharedMemorySize, SM_TOTAL);

    k_prep<<<128, 256>>>(cb);
    k_main<<<512, 256, SM_TOTAL>>>(z, cb, out);
    k_perp<<<1, 1024>>>(out);
    (void)out_size;
}

// round 9
// speedup vs baseline: 1.2451x; 1.2451x over previous
#include <cuda_runtime.h>
#include <cuda_bf16.h>
#include <math.h>
#include <stdint.h>

#define CNW 64
#define KN 1024
#define NPTS 65536
#define PLANE 1024
#define ZSZ 4194304
#define EPSV 1e-10f
#define TRIGM 1.5e-3f         // packed-bf16 trigger margin
#define EMITM 1.2e-3f         // f32 emission margin
#define LISTCAP 24
#define PITCHW 36             // u32 words per row in smem A/B tiles (64 bf16 + pad)

typedef unsigned long long ull;

__device__ float    g_cnorm[KN];
__device__ int      g_hist[KN];
__device__ unsigned g_cbbf[KN * 32];   // packed bf16 pairs, 32 words/row

// ---------------- smem layout (bytes) ----------------
// SM_A region is ALIASED by CAND/CNT/BESTS/FBROWS/FBCNT/FBBEST — those may only
// be touched AFTER the A fragments are loaded into registers.
#define SM_B0      0                       // 18432
#define SM_B1      18432                   // 18432
#define SM_EN      36864                   // float[1024] = 4096 (-norm/2)
#define SM_A       40960                   // 18432
#define SM_CAND    40960                   // u16[128*24] = 6144
#define SM_CNT     47104                   // int[128]
#define SM_BESTS   47616                   // int[128]
#define SM_FBROWS  48128                   // int[128]
#define SM_FBCNT   48640
#define SM_FBBEST  48648
#define SM_TOTAL   59392

// ---------------------------------------------------------------------------
__global__ void k_prep(const float* __restrict__ cb) {
    int row  = blockIdx.x * 8 + (threadIdx.x >> 5);
    int lane = threadIdx.x & 31;
    if (row >= KN) return;
    const float* r = cb + row * CNW;
    float e0 = r[2 * lane], e1 = r[2 * lane + 1];
    float s = __fmaf_rn(e0, e0, __fmul_rn(e1, e1));
    #pragma unroll
    for (int o = 16; o; o >>= 1) s += __shfl_xor_sync(0xffffffffu, s, o);
    g_cbbf[row * 32 + lane] =
        (unsigned)__bfloat16_as_ushort(__float2bfloat16(e0))
      | ((unsigned)__bfloat16_as_ushort(__float2bfloat16(e1)) << 16);
    if (lane == 0) { g_cnorm[row] = s; g_hist[row] = 0; }
}

// ---------------------------------------------------------------------------
__device__ __forceinline__ void mma16816(float& d0, float& d1, float& d2, float& d3,
                                         unsigned a0, unsigned a1, unsigned a2, unsigned a3,
                                         unsigned b0, unsigned b1) {
    asm volatile(
        "mma.sync.aligned.m16n8k16.row.col.f32.bf16.bf16.f32 "
        "{%0,%1,%2,%3}, {%4,%5,%6,%7}, {%8,%9}, {%0,%1,%2,%3};"
        : "+f"(d0), "+f"(d1), "+f"(d2), "+f"(d3)
        : "r"(a0), "r"(a1), "r"(a2), "r"(a3), "r"(b0), "r"(b1));
}

__device__ __forceinline__ unsigned pack_bf2(float lo, float hi) {
    unsigned p;
    asm("cvt.rn.bf16x2.f32 %0, %1, %2;" : "=r"(p) : "f"(hi), "f"(lo));
    return p;
}
__device__ __forceinline__ unsigned max_bf2(unsigned a, unsigned b) {
    unsigned m;
    asm("max.bf16x2 %0, %1, %2;" : "=r"(m) : "r"(a), "r"(b));
    return m;
}
__device__ __forceinline__ float bf2_lo(unsigned p) { return __uint_as_float(p << 16); }
__device__ __forceinline__ float bf2_hi(unsigned p) { return __uint_as_float(p & 0xffff0000u); }

// exact reference-rounded distance: d = RN(RN(xn+en) + RN(-2*dot)), seq fma chain
__device__ __forceinline__ float exactDist(const float* __restrict__ zp,
                                           const float* __restrict__ crow,
                                           float xn, float en) {
    float dot = 0.0f;
    #pragma unroll
    for (int c = 0; c < CNW; c++) dot = __fmaf_rn(zp[c * PLANE], crow[c], dot);
    return __fadd_rn(__fadd_rn(xn, en), __fmul_rn(-2.0f, dot));
}

// ---------------------------------------------------------------------------
// main: bf16 HMMA (argmax x.e - en/2, bias in accumulator init), chunk-deferred
// register-resident packed scan. CTA = 128 points, 256 threads, occ 2.
// ---------------------------------------------------------------------------
__global__ __launch_bounds__(256, 2)
void k_main(const float* __restrict__ z, const float* __restrict__ cb,
            float* __restrict__ out) {
    extern __shared__ char smem[];
    unsigned*       b0S = (unsigned*)(smem + SM_B0);
    unsigned*       b1S = (unsigned*)(smem + SM_B1);
    float*          enS = (float*)(smem + SM_EN);
    unsigned*       aS  = (unsigned*)(smem + SM_A);
    unsigned short* candK = (unsigned short*)(smem + SM_CAND);
    int* cnt    = (int*)(smem + SM_CNT);
    int* bests  = (int*)(smem + SM_BESTS);
    int* fbRows = (int*)(smem + SM_FBROWS);
    int* fbCnt  = (int*)(smem + SM_FBCNT);
    ull* fbBest = (ull*)(smem + SM_FBBEST);

    const int tid  = threadIdx.x;
    const int lane = tid & 31;
    const int warp = tid >> 5;
    const int n0   = blockIdx.x * 128;
    const float* zb = z + (size_t)(n0 >> 10) * (CNW * PLANE) + (n0 & 1023);

    // ---- stage A (z -> bf16 pairs, pitch 36) + en (-norm/2) + B chunk 0 ----
    for (int i = tid; i < 128 * 32; i += 256) {
        int j = i >> 7, p = i & 127;
        float lo = zb[(2 * j) * PLANE + p];
        float hi = zb[(2 * j + 1) * PLANE + p];
        aS[p * PITCHW + j] =
            (unsigned)__bfloat16_as_ushort(__float2bfloat16(lo))
          | ((unsigned)__bfloat16_as_ushort(__float2bfloat16(hi)) << 16);
    }
    for (int i = tid; i < KN; i += 256) enS[i] = -0.5f * g_cnorm[i];
    {
        const uint4* src = (const uint4*)g_cbbf;
        uint4* dst = (uint4*)b0S;
        for (int i = tid; i < 1024; i += 256) {
            int kr = i >> 3, q = i & 7;
            dst[kr * 9 + q] = src[i];
        }
    }
    __syncthreads();

    // ---- A fragments in registers ----
    const int r = lane >> 2, t = lane & 3;
    const int m0 = warp * 16;
    unsigned a[4][4];
    #pragma unroll
    for (int c5 = 0; c5 < 4; c5++) {
        int w0 = (m0 + r) * PITCHW + c5 * 8 + t;
        int w1 = w0 + 8 * PITCHW;
        a[c5][0] = aS[w0]; a[c5][1] = aS[w1];
        a[c5][2] = aS[w0 + 4]; a[c5][3] = aS[w1 + 4];
    }
    __syncthreads();     // A staging dead; aliased bookkeeping may now be init'd
    if (tid < 128) cnt[tid] = 0;
    if (tid == 128) *fbCnt = 0;
    __syncthreads();

    const int row0 = m0 + r, row1 = row0 + 8;
    float rm0 = -1e30f, rm1 = -1e30f;

    for (int ch = 0; ch < 8; ch++) {
        if (ch + 1 < 8) {   // stage next B chunk into the other buffer
            const uint4* src = (const uint4*)(g_cbbf + (size_t)(ch + 1) * 128 * 32);
            uint4* dst = (uint4*)(((ch + 1) & 1) ? b1S : b0S);
            for (int i = tid; i < 1024; i += 256) {
                int kr = i >> 3, q = i & 7;
                dst[kr * 9 + q] = src[i];
            }
        }
        const unsigned* bS = (ch & 1) ? b1S : b0S;
        const int kb = ch * 128;

        // ---- pass A: MMAs (bias-initialized acc), packed running max ----
        unsigned sc0[16], sc1[16];
        unsigned pm0 = 0xFF80FF80u, pm1 = 0xFF80FF80u;   // (-inf,-inf) bf16x2
        #pragma unroll
        for (int nt = 0; nt < 16; nt++) {
            float2 enh = *(const float2*)&enS[kb + nt * 8 + 2 * t];
            float d0 = enh.x, d1 = enh.y, d2 = enh.x, d3 = enh.y;
            const int base = (nt * 8 + r) * PITCHW + t;
            #pragma unroll
            for (int c5 = 0; c5 < 4; c5++) {
                unsigned bb0 = bS[base + c5 * 8];
                unsigned bb1 = bS[base + c5 * 8 + 4];
                mma16816(d0, d1, d2, d3,
                         a[c5][0], a[c5][1], a[c5][2], a[c5][3], bb0, bb1);
            }
            unsigned p0 = pack_bf2(d0, d1);   // row0: k0(lo), k0+1(hi)
            unsigned p1 = pack_bf2(d2, d3);   // row1
            pm0 = max_bf2(pm0, p0);
            pm1 = max_bf2(pm1, p1);
            sc0[nt] = p0; sc1[nt] = p1;
        }

        // ---- chunk max per row (quad reduce), monotone running max ----
        float m0f = fmaxf(bf2_lo(pm0), bf2_hi(pm0));
        float m1f = fmaxf(bf2_lo(pm1), bf2_hi(pm1));
        m0f = fmaxf(m0f, __shfl_xor_sync(0xffffffffu, m0f, 1));
        m0f = fmaxf(m0f, __shfl_xor_sync(0xffffffffu, m0f, 2));
        m1f = fmaxf(m1f, __shfl_xor_sync(0xffffffffu, m1f, 1));
        m1f = fmaxf(m1f, __shfl_xor_sync(0xffffffffu, m1f, 2));
        rm0 = fmaxf(rm0, m0f);
        rm1 = fmaxf(rm1, m1f);

        // ---- pass B: packed threshold scan of register scores ----
        const float th0e = rm0 - EMITM, th1e = rm1 - EMITM;
        const unsigned thr0 = pack_bf2(rm0 - TRIGM, rm0 - TRIGM);
        const unsigned thr1 = pack_bf2(rm1 - TRIGM, rm1 - TRIGM);
        #pragma unroll
        for (int nt = 0; nt < 16; nt++) {
            const int k0 = kb + nt * 8 + 2 * t;
            unsigned v0 = sc0[nt];
            if (max_bf2(v0, thr0) != thr0) {
                if (bf2_lo(v0) >= th0e) {
                    int pos = atomicAdd(&cnt[row0], 1);
                    if (pos < LISTCAP) candK[row0 * LISTCAP + pos] = (unsigned short)k0;
                }
                if (bf2_hi(v0) >= th0e) {
                    int pos = atomicAdd(&cnt[row0], 1);
                    if (pos < LISTCAP) candK[row0 * LISTCAP + pos] = (unsigned short)(k0 + 1);
                }
            }
            unsigned v1 = sc1[nt];
            if (max_bf2(v1, thr1) != thr1) {
                if (bf2_lo(v1) >= th1e) {
                    int pos = atomicAdd(&cnt[row1], 1);
                    if (pos < LISTCAP) candK[row1 * LISTCAP + pos] = (unsigned short)k0;
                }
                if (bf2_hi(v1) >= th1e) {
                    int pos = atomicAdd(&cnt[row1], 1);
                    if (pos < LISTCAP) candK[row1 * LISTCAP + pos] = (unsigned short)(k0 + 1);
                }
            }
        }
        __syncthreads();   // staged buffer visible; readers done before overwrite
    }

    // ---- phase 2: exact recheck (reference-rounded) ----
    if (tid < 128) {
        int c = cnt[tid];
        if (c > LISTCAP || c == 0) {
            fbRows[atomicAdd(fbCnt, 1)] = tid;
        } else {
            const float* zp = zb + tid;
            float xn = 0.0f;
            #pragma unroll
            for (int cc = 0; cc < CNW; cc++) {
                float x = zp[cc * PLANE];
                xn = __fadd_rn(xn, __fmul_rn(x, x));
            }
            float bd = 1e30f; int bk = 0x7fffffff;
            for (int j = 0; j < c; j++) {
                int k = candK[tid * LISTCAP + j];
                float d = exactDist(zp, cb + (size_t)k * CNW, xn, g_cnorm[k]);
                if (d < bd || (d == bd && k < bk)) { bd = d; bk = k; }
            }
            bests[tid] = bk;
            out[(size_t)2 * ZSZ + n0 + tid] = (float)bk;
            atomicAdd(&g_hist[bk], 1);
        }
    }
    __syncthreads();

    // ---- fallback: CTA-cooperative exact scan (provably-safe net, ~never) ----
    int nfb = *fbCnt;
    if (nfb > 128) nfb = 128;
    for (int f = 0; f < nfb; f++) {
        const int row = fbRows[f];
        if (tid == 0) *fbBest = ~0ull;
        __syncthreads();
        const float* zp = zb + row;
        float xn = 0.0f;
        #pragma unroll
        for (int cc = 0; cc < CNW; cc++) {
            float x = zp[cc * PLANE];
            xn = __fadd_rn(xn, __fmul_rn(x, x));
        }
        for (int k = tid; k < KN; k += 256) {
            float d = exactDist(zp, cb + (size_t)k * CNW, xn, g_cnorm[k]);
            ull pk = ((ull)__float_as_uint(d) << 32) | (unsigned)k;   // d > 0
            atomicMin(fbBest, pk);
        }
        __syncthreads();
        if (tid == 0) {
            int bk = (int)(*fbBest & 0xffffffffull);
            bests[row] = bk;
            out[(size_t)2 * ZSZ + n0 + row] = (float)bk;
            atomicAdd(&g_hist[bk], 1);
        }
        __syncthreads();
    }
    __syncthreads();

    // ---- phase 3: gather rows to smem (reuse B region), coalesced writes ----
    float* qs = (float*)(smem + SM_B0);   // 128 x pitch-65 floats = 33280B
    for (int i = tid; i < 128 * 64; i += 256) {
        int p = i >> 6, c = i & 63;
        qs[p * 65 + c] = cb[(size_t)bests[p] * CNW + c];
    }
    __syncthreads();
    const size_t obase = (size_t)(n0 >> 10) * (CNW * PLANE) + (n0 & 1023);
    for (int i = tid; i < 128 * 64; i += 256) {
        int c = i >> 7, p = i & 127;
        float q = qs[p * 65 + c];
        float x = zb[c * PLANE + p];
        size_t o = obase + (size_t)c * PLANE + p;
        out[o]       = q;
        out[o + ZSZ] = __fadd_rn(x, __fsub_rn(q, x));   // z + (q - z)
    }
}

// ---------------------------------------------------------------------------
__global__ void k_perp(float* __restrict__ out) {
    __shared__ float red[32];
    int t = threadIdx.x;
    float p = (float)g_hist[t] * (1.0f / (float)NPTS);
    float term = __fmul_rn(p, logf(fmaxf(p, EPSV)));
    #pragma unroll
    for (int o = 16; o; o >>= 1) term += __shfl_xor_sync(0xffffffffu, term, o);
    if ((t & 31) == 0) red[t >> 5] = term;
    __syncthreads();
    if (t < 32) {
        float s = red[t];
        #pragma unroll
        for (int o = 16; o; o >>= 1) s += __shfl_xor_sync(0xffffffffu, s, o);
        if (t == 0) out[(size_t)2 * ZSZ + NPTS] = expf(-s);
    }
}

// ---------------------------------------------------------------------------
extern "C" void kernel_launch(void* const* d_in, const int* in_sizes, int n_in,
                              void* d_out, int out_size) {
    const float* z  = (const float*)d_in[0];
    const float* cb = (const float*)d_in[1];
    if (n_in >= 2 && in_sizes[0] == KN * CNW && in_sizes[1] == ZSZ) {
        const float* tmp = z; z = cb; cb = tmp;
    }
    float* out = (float*)d_out;

    cudaFuncSetAttribute(k_main, cudaFuncAttributeMaxDynamicSharedMemorySize, SM_TOTAL);

    k_prep<<<128, 256>>>(cb);
    k_main<<<512, 256, SM_TOTAL>>>(z, cb, out);
    k_perp<<<1, 1024>>>(out);
    (void)out_size;
}